// round 4
// baseline (speedup 1.0000x reference)
#include <cuda_runtime.h>
#include <cstdint>
#include <math.h>

// ---------------- problem constants ----------------
#define B_    16
#define CIN   48
#define COUT  48
#define HH    128
#define WW    128
#define SP    7
#define TAPS  49
#define KDIM  98

// ---------------- tiling ----------------
#define CM     8                 // channels per K-chunk (K=8 per mma)
#define NCH    (CIN/CM)          // 6
#define RG     8                 // output rows per CTA
#define SLAB_RR 14               // RG + 6 halo
#define SLAB_CC 140              // 134 needed, padded
#define SLAB_FLOATS (SLAB_RR*SLAB_CC*CM)   // 15680
#define FILT_FLOATS (TAPS*COUT*CM)         // 18816
#define BIAS_OFF    (SLAB_FLOATS + FILT_FLOATS)          // 34496
#define SMEM_FLOATS (BIAS_OFF + 64)                      // 34560
#define SMEM_BYTES  (SMEM_FLOATS * 4)                    // 138240

#define NTHREADS 512

// filter scratch (permuted channel-minor, tf32-rounded): F[b][ch][tap][n][p8]
__device__ float g_F[(size_t)B_ * NCH * TAPS * COUT * CM];

// ---------------- helpers ----------------
__device__ __forceinline__ float tf32r(float f) {
    uint32_t u;
    asm("cvt.rna.tf32.f32 %0, %1;" : "=r"(u) : "f"(f));
    return __uint_as_float(u);
}

__device__ __forceinline__ void mma_tf32(float* c,
                                         uint32_t a0, uint32_t a1, uint32_t a2, uint32_t a3,
                                         uint32_t b0, uint32_t b1) {
    asm volatile(
        "mma.sync.aligned.m16n8k8.row.col.f32.tf32.tf32.f32 "
        "{%0,%1,%2,%3},{%4,%5,%6,%7},{%8,%9},{%0,%1,%2,%3};"
        : "+f"(c[0]), "+f"(c[1]), "+f"(c[2]), "+f"(c[3])
        : "r"(a0), "r"(a1), "r"(a2), "r"(a3), "r"(b0), "r"(b1));
}

// ---------------------------------------------------------------------------
// Kernel A v2: filter generation, basis shared across taps.
// Block = (nq, b): computes all 49 taps x 12 n x 48 m. W slice read once.
// F[b][ch][tap][n][p] = tf32( sum_k basis[tap,k] * W[n][k][m] ),
// p = 2*(mm&3) + (mm>>2)
// ---------------------------------------------------------------------------
__global__ __launch_bounds__(256)
void gen_filters_kernel(const float* __restrict__ theta,
                        const float* __restrict__ W)
{
    __shared__ float bs[TAPS][KDIM];

    const int nq = blockIdx.x;          // 0..3  (12 n-values each)
    const int b  = blockIdx.y;
    const int t  = threadIdx.x;

    const float th = theta[b];
    const float ct = cosf(th), st = sinf(th);

    // phase 1: basis table 49 x 98
    for (int e = t; e < TAPS * KDIM; e += 256) {
        const int tap = e / KDIM;
        const int q   = e - tap * KDIM;
        const int i   = tap / SP;
        const int j   = tap % SP;
        const float xj = (float)(j - 3) * (1.0f / 3.0f);
        const float xi = (float)(i - 3) * (1.0f / 3.0f);
        const float Xr = ct * xj - st * xi;
        const float Yr = st * xj + ct * xi;
        const float r2 = Xr * Xr + Yr * Yr;
        const float mask = expf(-fmaxf(r2 - 1.0f, 0.0f) * 5.0f);

        const bool cosp = (q < TAPS);
        const int  qq   = cosp ? q : q - TAPS;
        const int  k    = qq / SP;
        const int  l    = qq % SP;
        const float kk = (k > 3) ? (float)(k - SP) : (float)k;
        const float ll = (l > 3) ? (float)(l - SP) : (float)l;
        const float v  = 2.6927937030769655f;   // pi/7 * 6
        const float ang = kk * v * Xr + ll * v * Yr;
        bs[tap][q] = (cosp ? cosf(ang) : sinf(ang)) * mask;
    }
    __syncthreads();

    // phase 2: 49 taps x 12 n x 48 m dot products (m consecutive -> coalesced W)
    const int n0 = nq * 12;
    for (int o = t; o < TAPS * 12 * CIN; o += 256) {
        const int tap = o / (12 * CIN);
        const int rem = o - tap * (12 * CIN);
        const int nn  = rem / CIN;
        const int m   = rem - nn * CIN;
        const int n   = n0 + nn;
        const float* wp = W + (size_t)n * KDIM * CIN + m;
        const float* bp = bs[tap];
        float s = 0.0f;
        #pragma unroll 7
        for (int k = 0; k < KDIM; ++k)
            s += bp[k] * wp[(size_t)k * CIN];
        const int ch = m >> 3, mm = m & 7;
        const int p  = 2 * (mm & 3) + (mm >> 2);
        g_F[((((size_t)b * NCH + ch) * TAPS + tap) * COUT + n) * CM + p] = tf32r(s);
    }
}

// ---------------------------------------------------------------------------
// Kernel B: tf32 mma.sync implicit-GEMM grouped conv.
// CTA = (b, 8 output rows), 512 threads / 16 warps.
// warp w -> row (w>>1), cols 64*(w&1)..+63.  Warp tile M=64 px x N=48.
// ---------------------------------------------------------------------------
__global__ __launch_bounds__(NTHREADS, 1)
void conv_mma_kernel(const float* __restrict__ x,
                     const float* __restrict__ cbias,
                     float* __restrict__ y)
{
    extern __shared__ float sm[];
    float* slab = sm;                 // [14][140][8] permuted channels
    float* filt = sm + SLAB_FLOATS;   // [49][48][8] permuted channels
    float* bias = sm + BIAS_OFF;

    const int tid  = threadIdx.x;
    const int wid  = tid >> 5;
    const int lane = tid & 31;
    const int b    = blockIdx.x >> 4;
    const int rg   = blockIdx.x & 15;
    const int h0   = rg * RG;

    const int g  = lane >> 2;         // group id 0..7
    const int t4 = lane & 3;          // thread-in-group
    const int rw   = wid >> 1;        // warp row 0..7
    const int col0 = (wid & 1) * 64;  // warp col base

    if (tid < COUT) bias[tid] = cbias[tid];

    float acc[4][6][4];
    #pragma unroll
    for (int mt = 0; mt < 4; ++mt)
        #pragma unroll
        for (int nt = 0; nt < 6; ++nt)
            #pragma unroll
            for (int q = 0; q < 4; ++q)
                acc[mt][nt][q] = 0.0f;

    const float* xb = x + (size_t)b * CIN * HH * WW;

    #pragma unroll 1
    for (int ch = 0; ch < NCH; ++ch) {
        __syncthreads();
        // zero slab (halo stays zero)
        for (int q = tid; q < SLAB_FLOATS / 4; q += NTHREADS)
            ((float4*)slab)[q] = make_float4(0.f, 0.f, 0.f, 0.f);
        __syncthreads();

        // fill slab interior: S[rr][3+gc][perm(mm)] = tf32(x[b][8ch+mm][h0-3+rr][gc])
        const float* xc = xb + (size_t)ch * CM * HH * WW;
        for (int q = tid; q < CM * SLAB_RR * 32; q += NTHREADS) {
            const int quad = q & 31;
            const int r2   = q >> 5;            // 0..111
            const int mm   = r2 / SLAB_RR;
            const int rr   = r2 - mm * SLAB_RR;
            const int gr   = h0 - 3 + rr;
            if (gr >= 0 && gr < HH) {
                const float4 v = *(const float4*)(xc + ((size_t)mm * HH + gr) * WW + 4 * quad);
                const int p = 2 * (mm & 3) + (mm >> 2);
                float* d = slab + (rr * SLAB_CC + 3 + 4 * quad) * CM + p;
                d[0]      = tf32r(v.x);
                d[CM]     = tf32r(v.y);
                d[2 * CM] = tf32r(v.z);
                d[3 * CM] = tf32r(v.w);
            }
        }
        // stage filters for this chunk (already permuted + tf32-rounded)
        {
            const float4* Fs = (const float4*)(g_F + (size_t)(b * NCH + ch) * TAPS * COUT * CM);
            float4* fd = (float4*)filt;
            for (int q = tid; q < FILT_FLOATS / 4; q += NTHREADS)
                fd[q] = Fs[q];
        }
        __syncthreads();

        #pragma unroll 1
        for (int i = 0; i < SP; ++i) {
            const int abase = (rw + i) * (SLAB_CC * CM);
            #pragma unroll
            for (int j = 0; j < SP; ++j) {
                const int tap = i * SP + j;
                // B fragments: filt[tap][n = nt*8+g][2*t4 .. +1]
                uint2 Bf[6];
                #pragma unroll
                for (int nt = 0; nt < 6; ++nt)
                    Bf[nt] = *(const uint2*)&filt[(tap * COUT + nt * 8 + g) * CM + 2 * t4];
                #pragma unroll
                for (int mt = 0; mt < 4; ++mt) {
                    const int ai = abase + (col0 + mt * 16 + g + j) * CM + 2 * t4;
                    const uint2 a02 = *(const uint2*)&slab[ai];           // px = g
                    const uint2 a13 = *(const uint2*)&slab[ai + 8 * CM];  // px = g+8
                    #pragma unroll
                    for (int nt = 0; nt < 6; ++nt)
                        mma_tf32(acc[mt][nt], a02.x, a13.x, a02.y, a13.y,
                                 Bf[nt].x, Bf[nt].y);
                }
            }
        }
    }

    // epilogue
    const int row = h0 + rw;
    #pragma unroll
    for (int nt = 0; nt < 6; ++nt) {
        const int n  = nt * 8 + 2 * t4;
        const float b0 = bias[n];
        const float b1 = bias[n + 1];
        float* y0 = y + (((size_t)b * COUT + n) * HH + row) * WW;
        float* y1 = y0 + (size_t)HH * WW;
        #pragma unroll
        for (int mt = 0; mt < 4; ++mt) {
            const int px = col0 + mt * 16 + g;
            y0[px]     = acc[mt][nt][0] + b0;
            y1[px]     = acc[mt][nt][1] + b1;
            y0[px + 8] = acc[mt][nt][2] + b0;
            y1[px + 8] = acc[mt][nt][3] + b1;
        }
    }
}

// ---------------------------------------------------------------------------
extern "C" void kernel_launch(void* const* d_in, const int* in_sizes, int n_in,
                              void* d_out, int out_size)
{
    const float* x     = (const float*)d_in[0];  // (16,48,128,128)
    const float* theta = (const float*)d_in[1];  // (16,1)
    const float* wts   = (const float*)d_in[2];  // (48,98,48)
    const float* cbias = (const float*)d_in[3];  // (1,48,1,1)
    float*       y     = (float*)d_out;          // (16,48,128,128)

    (void)in_sizes; (void)n_in; (void)out_size;

    static int smem_set = 0;
    if (!smem_set) {
        cudaFuncSetAttribute(conv_mma_kernel,
                             cudaFuncAttributeMaxDynamicSharedMemorySize, SMEM_BYTES);
        smem_set = 1;
    }

    dim3 ggrid(4, B_);
    gen_filters_kernel<<<ggrid, 256>>>(theta, wts);
    conv_mma_kernel<<<B_ * 16, NTHREADS, SMEM_BYTES>>>(x, cbias, y);
}

// round 5
// speedup vs baseline: 1.3986x; 1.3986x over previous
#include <cuda_runtime.h>
#include <cstdint>
#include <math.h>

// ---------------- problem constants ----------------
#define B_    16
#define CIN   48
#define COUT  48
#define HH    128
#define WW    128
#define SP    7
#define TAPS  49
#define KDIM  98

// ---------------- tiling ----------------
#define CM     8                 // channels per K-chunk (K=8 per mma)
#define NCH    (CIN/CM)          // 6
#define RG     4                 // output rows per CTA
#define SLAB_RR 10               // RG + 6 halo
#define SLAB_CC 140
#define SLAB_FLOATS (SLAB_RR*SLAB_CC*CM)   // 11200
#define SMEM_BYTES  (SLAB_FLOATS*4)        // 44800

// filter scratch (permuted channel-minor, tf32-rounded): F[b][ch][tap][n][p8]
__device__ float g_F[(size_t)B_ * NCH * TAPS * COUT * CM];

// ---------------- helpers ----------------
__device__ __forceinline__ float tf32r(float f) {
    uint32_t u;
    asm("cvt.rna.tf32.f32 %0, %1;" : "=r"(u) : "f"(f));
    return __uint_as_float(u);
}

__device__ __forceinline__ void mma_tf32(float* c,
                                         uint32_t a0, uint32_t a1, uint32_t a2, uint32_t a3,
                                         uint32_t b0, uint32_t b1) {
    asm volatile(
        "mma.sync.aligned.m16n8k8.row.col.f32.tf32.tf32.f32 "
        "{%0,%1,%2,%3},{%4,%5,%6,%7},{%8,%9},{%0,%1,%2,%3};"
        : "+f"(c[0]), "+f"(c[1]), "+f"(c[2]), "+f"(c[3])
        : "r"(a0), "r"(a1), "r"(a2), "r"(a3), "r"(b0), "r"(b1));
}

// ---------------------------------------------------------------------------
// Kernel A v3: filter generation with register-resident W reuse.
// Block = (nh, ch, b); 96 threads; thread owns columns (n, n+12) for fixed mm.
// acc[49] per column: W element loaded once, reused for all 49 taps.
// W L2 traffic: each element read once per (b) -> 16 x 903KB = 14.5 MB.
// ---------------------------------------------------------------------------
__global__ __launch_bounds__(96)
void gen_filters_kernel(const float* __restrict__ theta,
                        const float* __restrict__ W)
{
    __shared__ float bs[TAPS][KDIM];

    const int nh = blockIdx.x;          // 0..1 (24 n each)
    const int ch = blockIdx.y;          // 0..5
    const int b  = blockIdx.z;
    const int t  = threadIdx.x;

    const float th = theta[b];
    const float ct = cosf(th), st = sinf(th);

    // phase 1: basis table 49 x 98
    for (int e = t; e < TAPS * KDIM; e += 96) {
        const int tap = e / KDIM;
        const int q   = e - tap * KDIM;
        const int i   = tap / SP;
        const int j   = tap % SP;
        const float xj = (float)(j - 3) * (1.0f / 3.0f);
        const float xi = (float)(i - 3) * (1.0f / 3.0f);
        const float Xr = ct * xj - st * xi;
        const float Yr = st * xj + ct * xi;
        const float r2 = Xr * Xr + Yr * Yr;
        const float mask = expf(-fmaxf(r2 - 1.0f, 0.0f) * 5.0f);

        const bool cosp = (q < TAPS);
        const int  qq   = cosp ? q : q - TAPS;
        const int  k    = qq / SP;
        const int  l    = qq % SP;
        const float kk = (k > 3) ? (float)(k - SP) : (float)k;
        const float ll = (l > 3) ? (float)(l - SP) : (float)l;
        const float v  = 2.6927937030769655f;   // pi/7 * 6
        const float ang = kk * v * Xr + ll * v * Yr;
        bs[tap][q] = (cosp ? cosf(ang) : sinf(ang)) * mask;
    }
    __syncthreads();

    // phase 2: 2 columns per thread, 49 accumulators each
    const int nn = t >> 3;              // 0..11
    const int mm = t & 7;
    const int m  = ch * CM + mm;
    const int n0 = nh * 24 + nn;        // and n0+12

    float acc0[TAPS], acc1[TAPS];
    #pragma unroll
    for (int tap = 0; tap < TAPS; ++tap) { acc0[tap] = 0.f; acc1[tap] = 0.f; }

    const float* w0 = W + (size_t)n0 * KDIM * CIN + m;
    const float* w1 = w0 + (size_t)12 * KDIM * CIN;

    #pragma unroll 2
    for (int k = 0; k < KDIM; ++k) {
        const float v0 = w0[(size_t)k * CIN];
        const float v1 = w1[(size_t)k * CIN];
        #pragma unroll
        for (int tap = 0; tap < TAPS; ++tap) {
            const float f = bs[tap][k];
            acc0[tap] = fmaf(f, v0, acc0[tap]);
            acc1[tap] = fmaf(f, v1, acc1[tap]);
        }
    }

    const int p = 2 * (mm & 3) + (mm >> 2);
    float* Fo = g_F + ((size_t)(b * NCH + ch) * TAPS) * COUT * CM + p;
    #pragma unroll
    for (int tap = 0; tap < TAPS; ++tap) {
        Fo[(size_t)tap * COUT * CM + n0 * CM]        = tf32r(acc0[tap]);
        Fo[(size_t)tap * COUT * CM + (n0 + 12) * CM] = tf32r(acc1[tap]);
    }
}

// ---------------------------------------------------------------------------
// Kernel B: tf32 mma.sync implicit-GEMM grouped conv.
// CTA = (b, 4 output rows), 256 threads / 8 warps; 2 CTAs per SM.
// warp w -> row (w>>1), cols 64*(w&1)..+63.  Warp tile M=64 px x N=48.
// A frags from smem slab (permuted channel-minor); B frags via LDG from g_F
// (L1-resident 75KB chunk slice). Slab zeroed once; 2 barriers per chunk.
// ---------------------------------------------------------------------------
__global__ __launch_bounds__(256, 2)
void conv_mma_kernel(const float* __restrict__ x,
                     const float* __restrict__ cbias,
                     float* __restrict__ y)
{
    __shared__ float slab[SLAB_FLOATS];   // [10][140][8] permuted channels

    const int tid  = threadIdx.x;
    const int wid  = tid >> 5;
    const int lane = tid & 31;
    const int b    = blockIdx.x >> 5;
    const int rg   = blockIdx.x & 31;
    const int h0   = rg * RG;

    const int g  = lane >> 2;         // group id 0..7
    const int t4 = lane & 3;          // thread-in-group
    const int rw   = wid >> 1;        // warp row 0..3
    const int col0 = (wid & 1) * 64;  // warp col base

    float acc[4][6][4];
    #pragma unroll
    for (int mt = 0; mt < 4; ++mt)
        #pragma unroll
        for (int nt = 0; nt < 6; ++nt)
            #pragma unroll
            for (int q = 0; q < 4; ++q)
                acc[mt][nt][q] = 0.0f;

    // zero slab once (halo + out-of-range rows stay zero forever)
    for (int q = tid; q < SLAB_FLOATS / 4; q += 256)
        ((float4*)slab)[q] = make_float4(0.f, 0.f, 0.f, 0.f);
    __syncthreads();

    const float* xb = x + (size_t)b * CIN * HH * WW;
    const float* Fb = g_F + (size_t)b * NCH * TAPS * COUT * CM;

    // per-thread fill coords: mm innermost (4-way STS banks, not 32-way)
    const int f_mm   = tid & 7;
    const int f_quad = (tid >> 3) & 31;
    const int f_p    = 2 * (f_mm & 3) + (f_mm >> 2);

    #pragma unroll 1
    for (int ch = 0; ch < NCH; ++ch) {
        // fill slab interior: S[rr][3+gc][perm(mm)] = tf32(x[b][8ch+mm][h0-3+rr][gc])
        const float* xc = xb + (size_t)ch * CM * HH * WW;
        #pragma unroll 1
        for (int rr = 0; rr < SLAB_RR; ++rr) {
            const int gr = h0 - 3 + rr;
            if (gr >= 0 && gr < HH) {
                const float4 v = *(const float4*)(xc + ((size_t)f_mm * HH + gr) * WW + 4 * f_quad);
                float* d = slab + (rr * SLAB_CC + 3 + 4 * f_quad) * CM + f_p;
                d[0]      = tf32r(v.x);
                d[CM]     = tf32r(v.y);
                d[2 * CM] = tf32r(v.z);
                d[3 * CM] = tf32r(v.w);
            }
        }
        __syncthreads();

        const float* Fch = Fb + (size_t)ch * TAPS * COUT * CM + g * CM + 2 * t4;

        #pragma unroll 1
        for (int i = 0; i < SP; ++i) {
            const int abase = (rw + i) * (SLAB_CC * CM);
            #pragma unroll
            for (int j = 0; j < SP; ++j) {
                const int tap = i * SP + j;
                const float* Ft = Fch + tap * (COUT * CM);
                uint2 Bf[6];
                #pragma unroll
                for (int nt = 0; nt < 6; ++nt)
                    Bf[nt] = __ldg((const uint2*)(Ft + nt * 8 * CM));
                #pragma unroll
                for (int mt = 0; mt < 4; ++mt) {
                    const int ai = abase + (col0 + mt * 16 + g + j) * CM + 2 * t4;
                    const uint2 a02 = *(const uint2*)&slab[ai];           // px = g
                    const uint2 a13 = *(const uint2*)&slab[ai + 8 * CM];  // px = g+8
                    #pragma unroll
                    for (int nt = 0; nt < 6; ++nt)
                        mma_tf32(acc[mt][nt], a02.x, a13.x, a02.y, a13.y,
                                 Bf[nt].x, Bf[nt].y);
                }
            }
        }
        __syncthreads();   // MMAs done before next chunk overwrites slab
    }

    // epilogue
    const int row = h0 + rw;
    #pragma unroll
    for (int nt = 0; nt < 6; ++nt) {
        const int n  = nt * 8 + 2 * t4;
        const float b0 = __ldg(&cbias[n]);
        const float b1 = __ldg(&cbias[n + 1]);
        float* y0 = y + (((size_t)b * COUT + n) * HH + row) * WW;
        float* y1 = y0 + (size_t)HH * WW;
        #pragma unroll
        for (int mt = 0; mt < 4; ++mt) {
            const int px = col0 + mt * 16 + g;
            y0[px]     = acc[mt][nt][0] + b0;
            y1[px]     = acc[mt][nt][1] + b1;
            y0[px + 8] = acc[mt][nt][2] + b0;
            y1[px + 8] = acc[mt][nt][3] + b1;
        }
    }
}

// ---------------------------------------------------------------------------
extern "C" void kernel_launch(void* const* d_in, const int* in_sizes, int n_in,
                              void* d_out, int out_size)
{
    const float* x     = (const float*)d_in[0];  // (16,48,128,128)
    const float* theta = (const float*)d_in[1];  // (16,1)
    const float* wts   = (const float*)d_in[2];  // (48,98,48)
    const float* cbias = (const float*)d_in[3];  // (1,48,1,1)
    float*       y     = (float*)d_out;          // (16,48,128,128)

    (void)in_sizes; (void)n_in; (void)out_size;

    dim3 ggrid(2, NCH, B_);
    gen_filters_kernel<<<ggrid, 96>>>(theta, wts);
    conv_mma_kernel<<<B_ * 32, 256>>>(x, cbias, y);
}

// round 6
// speedup vs baseline: 2.8858x; 2.0633x over previous
#include <cuda_runtime.h>
#include <cuda_fp16.h>
#include <cstdint>
#include <math.h>

// ---------------- problem constants ----------------
#define B_    16
#define CIN   48
#define COUT  48
#define HH    128
#define WW    128
#define SP    7
#define TAPS  49
#define KDIM  98

// ---------------- tiling ----------------
#define NCHUNK 3                  // chunks of 16 channels (K=16 per mma)
#define RG     8                  // output rows per CTA
#define SLAB_RR 14                // RG + 6 halo
#define SLAB_CC 136               // 134 needed, padded
// slab: [2 planes][SLAB_RR][SLAB_CC][8 halves]  (plane = 8-channel group)
#define APLANE_B   (SLAB_RR*SLAB_CC*8*2)          // 30464 bytes per plane
#define SLAB_BYTES (2*APLANE_B)                   // 60928
// filt: [tap][2 planes][48 n][8 halves]
#define FILT_BYTES (TAPS*2*48*8*2)                // 75264
#define SMEM_BYTES (SLAB_BYTES + FILT_BYTES)      // 136192

#define NTHREADS 512

// filter scratch, conv-staging order: g_F[b][chunk3][tap][plane2][n48][mm8] (fp16)
__device__ __half g_F[(size_t)B_ * NCHUNK * TAPS * 2 * 48 * 8];

// ---------------- helpers ----------------
__device__ __forceinline__ void mma_f16(float* c, uint32_t a0, uint32_t a1,
                                        uint32_t a2, uint32_t a3,
                                        uint32_t b0, uint32_t b1) {
    asm volatile(
        "mma.sync.aligned.m16n8k16.row.col.f32.f16.f16.f32 "
        "{%0,%1,%2,%3},{%4,%5,%6,%7},{%8,%9},{%0,%1,%2,%3};"
        : "+f"(c[0]), "+f"(c[1]), "+f"(c[2]), "+f"(c[3])
        : "r"(a0), "r"(a1), "r"(a2), "r"(a3), "r"(b0), "r"(b1));
}
__device__ __forceinline__ void ldsm_x4(uint32_t& r0, uint32_t& r1,
                                        uint32_t& r2, uint32_t& r3, uint32_t addr) {
    asm volatile("ldmatrix.sync.aligned.m8n8.x4.shared.b16 {%0,%1,%2,%3}, [%4];"
                 : "=r"(r0), "=r"(r1), "=r"(r2), "=r"(r3) : "r"(addr));
}
__device__ __forceinline__ void ldsm_x2(uint32_t& r0, uint32_t& r1, uint32_t addr) {
    asm volatile("ldmatrix.sync.aligned.m8n8.x2.shared.b16 {%0,%1}, [%2];"
                 : "=r"(r0), "=r"(r1) : "r"(addr));
}

// ---------------------------------------------------------------------------
// Kernel A: filter generation (register-tiled W reuse, fp16 output).
// Block = (nh, ch, b); 96 threads; thread owns columns (n, n+12) for fixed mm.
// ---------------------------------------------------------------------------
__global__ __launch_bounds__(96)
void gen_filters_kernel(const float* __restrict__ theta,
                        const float* __restrict__ W)
{
    __shared__ float bs[TAPS][KDIM];

    const int nh = blockIdx.x;          // 0..1 (24 n each)
    const int ch = blockIdx.y;          // 0..5 (8-channel groups)
    const int b  = blockIdx.z;
    const int t  = threadIdx.x;

    const float th = theta[b];
    const float ct = cosf(th), st = sinf(th);

    for (int e = t; e < TAPS * KDIM; e += 96) {
        const int tap = e / KDIM;
        const int q   = e - tap * KDIM;
        const int i   = tap / SP;
        const int j   = tap % SP;
        const float xj = (float)(j - 3) * (1.0f / 3.0f);
        const float xi = (float)(i - 3) * (1.0f / 3.0f);
        const float Xr = ct * xj - st * xi;
        const float Yr = st * xj + ct * xi;
        const float r2 = Xr * Xr + Yr * Yr;
        const float mask = expf(-fmaxf(r2 - 1.0f, 0.0f) * 5.0f);

        const bool cosp = (q < TAPS);
        const int  qq   = cosp ? q : q - TAPS;
        const int  k    = qq / SP;
        const int  l    = qq % SP;
        const float kk = (k > 3) ? (float)(k - SP) : (float)k;
        const float ll = (l > 3) ? (float)(l - SP) : (float)l;
        const float v  = 2.6927937030769655f;   // pi/7 * 6
        const float ang = kk * v * Xr + ll * v * Yr;
        bs[tap][q] = (cosp ? cosf(ang) : sinf(ang)) * mask;
    }
    __syncthreads();

    const int nn = t >> 3;              // 0..11
    const int mm = t & 7;
    const int m  = ch * 8 + mm;
    const int n0 = nh * 24 + nn;        // and n0+12

    float acc0[TAPS], acc1[TAPS];
    #pragma unroll
    for (int tap = 0; tap < TAPS; ++tap) { acc0[tap] = 0.f; acc1[tap] = 0.f; }

    const float* w0 = W + (size_t)n0 * KDIM * CIN + m;
    const float* w1 = w0 + (size_t)12 * KDIM * CIN;

    #pragma unroll 2
    for (int k = 0; k < KDIM; ++k) {
        const float v0 = w0[(size_t)k * CIN];
        const float v1 = w1[(size_t)k * CIN];
        #pragma unroll
        for (int tap = 0; tap < TAPS; ++tap) {
            const float f = bs[tap][k];
            acc0[tap] = fmaf(f, v0, acc0[tap]);
            acc1[tap] = fmaf(f, v1, acc1[tap]);
        }
    }

    // g_F[b][chunk][tap][plane][n][mm], chunk = ch>>1, plane = ch&1
    const int chunk = ch >> 1, plane = ch & 1;
    __half* Fo = g_F + ((((size_t)(b * NCHUNK + chunk) * TAPS) * 2 + plane) * 48) * 8 + mm;
    #pragma unroll
    for (int tap = 0; tap < TAPS; ++tap) {
        __half* Ft = Fo + (size_t)tap * (2 * 48 * 8);
        Ft[(size_t)n0 * 8]        = __float2half_rn(acc0[tap]);
        Ft[(size_t)(n0 + 12) * 8] = __float2half_rn(acc1[tap]);
    }
}

// ---------------------------------------------------------------------------
// Kernel B: fp16 m16n8k16 implicit-GEMM grouped conv.
// CTA = (b, 8 rows), 512 threads / 16 warps. warp w -> row (w>>1), col half (w&1).
// Warp tile M=64 px x N=48, K=16 per mma. A/B frags via ldmatrix from
// 8-channel "planes" (16B-dense rows, conflict-free).
// ---------------------------------------------------------------------------
__global__ __launch_bounds__(NTHREADS, 1)
void conv_mma_kernel(const float* __restrict__ x,
                     const float* __restrict__ cbias,
                     float* __restrict__ y)
{
    extern __shared__ __align__(16) unsigned char smraw[];
    __half*  slab_h   = (__half*)smraw;
    __half*  filt_h   = (__half*)(smraw + SLAB_BYTES);
    uint32_t smem_u32 = (uint32_t)__cvta_generic_to_shared(smraw);
    const uint32_t slab_u = smem_u32;
    const uint32_t filt_u = smem_u32 + SLAB_BYTES;

    const int tid  = threadIdx.x;
    const int wid  = tid >> 5;
    const int lane = tid & 31;
    const int b    = blockIdx.x >> 4;
    const int rg   = blockIdx.x & 15;
    const int h0   = rg * RG;

    const int g  = lane >> 2;
    const int t4 = lane & 3;
    const int rw   = wid >> 1;        // warp row 0..7
    const int col0 = (wid & 1) * 64;  // warp col base

    // ldmatrix lane-address invariants
    const int a_l16 = lane & 15;
    const int a_pl  = lane >> 4;                       // A plane select
    const uint32_t a_lane_base = slab_u + a_pl * APLANE_B + a_l16 * 16;
    const int bl     = lane & 15;
    const int b_pl   = bl >> 3;                        // B plane select
    const int b_row  = bl & 7;
    const uint32_t b_lane_base = filt_u + b_pl * (48 * 16) + b_row * 16;

    float acc[4][6][4];
    #pragma unroll
    for (int mt = 0; mt < 4; ++mt)
        #pragma unroll
        for (int nt = 0; nt < 6; ++nt)
            #pragma unroll
            for (int q = 0; q < 4; ++q)
                acc[mt][nt][q] = 0.0f;

    // zero slab once (halo + out-of-range rows stay zero)
    for (int q = tid; q < SLAB_BYTES / 16; q += NTHREADS)
        ((uint4*)smraw)[q] = make_uint4(0, 0, 0, 0);
    __syncthreads();

    const float* xb = x + (size_t)b * CIN * HH * WW;
    const __half* Fb = g_F + (size_t)b * NCHUNK * TAPS * 2 * 48 * 8;

    // fill mapping: one float4 per (plane, mm, quad) per rr
    const int f_mm   = tid & 7;
    const int f_quad = (tid >> 3) & 31;
    const int f_pl   = (tid >> 8) & 1;

    #pragma unroll 1
    for (int chk = 0; chk < NCHUNK; ++chk) {
        // ---- fill slab: slab[f_pl][rr][3+4q..][f_mm] = f16(x[ch][gr][gc]) ----
        const float* xc = xb + (size_t)(chk * 16 + f_pl * 8 + f_mm) * HH * WW;
        __half* dbase = slab_h + (size_t)f_pl * (APLANE_B / 2) + (3 + 4 * f_quad) * 8 + f_mm;
        #pragma unroll 1
        for (int rr = 0; rr < SLAB_RR; ++rr) {
            const int gr = h0 - 3 + rr;
            if (gr >= 0 && gr < HH) {
                const float4 v = *(const float4*)(xc + (size_t)gr * WW + 4 * f_quad);
                __half* d = dbase + rr * (SLAB_CC * 8);
                d[0]  = __float2half_rn(v.x);
                d[8]  = __float2half_rn(v.y);
                d[16] = __float2half_rn(v.z);
                d[24] = __float2half_rn(v.w);
            }
        }
        // ---- stage filters (straight copy, already conv-ordered) ----
        {
            const uint4* Fs = (const uint4*)(Fb + (size_t)chk * TAPS * 2 * 48 * 8);
            uint4* fd = (uint4*)filt_h;
            for (int q = tid; q < FILT_BYTES / 16; q += NTHREADS)
                fd[q] = Fs[q];
        }
        __syncthreads();

        #pragma unroll 1
        for (int i = 0; i < SP; ++i) {
            const uint32_t a_row = a_lane_base + ((rw + i) * SLAB_CC) * 16;
            #pragma unroll
            for (int j = 0; j < SP; ++j) {
                const int tap = i * SP + j;
                const uint32_t b_tap = b_lane_base + tap * (2 * 48 * 16);
                uint32_t Bf[6][2];
                #pragma unroll
                for (int nt = 0; nt < 6; ++nt)
                    ldsm_x2(Bf[nt][0], Bf[nt][1], b_tap + nt * (8 * 16));
                #pragma unroll
                for (int mt = 0; mt < 4; ++mt) {
                    uint32_t a0, a1, a2, a3;
                    ldsm_x4(a0, a1, a2, a3, a_row + (col0 + mt * 16 + j) * 16);
                    #pragma unroll
                    for (int nt = 0; nt < 6; ++nt)
                        mma_f16(acc[mt][nt], a0, a1, a2, a3, Bf[nt][0], Bf[nt][1]);
                }
            }
        }
        __syncthreads();   // MMAs done before next chunk overwrites slab/filt
    }

    // ---- epilogue ----
    const int row = h0 + rw;
    #pragma unroll
    for (int nt = 0; nt < 6; ++nt) {
        const int n  = nt * 8 + 2 * t4;
        const float b0 = __ldg(&cbias[n]);
        const float b1 = __ldg(&cbias[n + 1]);
        float* y0 = y + (((size_t)b * COUT + n) * HH + row) * WW;
        float* y1 = y0 + (size_t)HH * WW;
        #pragma unroll
        for (int mt = 0; mt < 4; ++mt) {
            const int px = col0 + mt * 16 + g;
            y0[px]     = acc[mt][nt][0] + b0;
            y1[px]     = acc[mt][nt][1] + b1;
            y0[px + 8] = acc[mt][nt][2] + b0;
            y1[px + 8] = acc[mt][nt][3] + b1;
        }
    }
}

// ---------------------------------------------------------------------------
extern "C" void kernel_launch(void* const* d_in, const int* in_sizes, int n_in,
                              void* d_out, int out_size)
{
    const float* x     = (const float*)d_in[0];  // (16,48,128,128)
    const float* theta = (const float*)d_in[1];  // (16,1)
    const float* wts   = (const float*)d_in[2];  // (48,98,48)
    const float* cbias = (const float*)d_in[3];  // (1,48,1,1)
    float*       y     = (float*)d_out;          // (16,48,128,128)

    (void)in_sizes; (void)n_in; (void)out_size;

    static int smem_set = 0;
    if (!smem_set) {
        cudaFuncSetAttribute(conv_mma_kernel,
                             cudaFuncAttributeMaxDynamicSharedMemorySize, SMEM_BYTES);
        smem_set = 1;
    }

    dim3 ggrid(2, 6, B_);
    gen_filters_kernel<<<ggrid, 96>>>(theta, wts);
    conv_mma_kernel<<<B_ * 16, NTHREADS, SMEM_BYTES>>>(x, cbias, y);
}

// round 7
// speedup vs baseline: 3.0609x; 1.0607x over previous
#include <cuda_runtime.h>
#include <cuda_fp16.h>
#include <cstdint>
#include <math.h>

// ---------------- problem constants ----------------
#define B_    16
#define CIN   48
#define COUT  48
#define HH    128
#define WW    128
#define SP    7
#define TAPS  49
#define KDIM  98

// ---------------- tiling ----------------
#define NCHUNK 3                   // chunks of 16 channels (K=16 per mma)
#define RG     8                   // output rows per CTA
#define SLAB_RR 14                 // RG + 6 halo
#define SLAB_CC 134                // 128 + 6 halo
#define PLANE_B (SLAB_RR*SLAB_CC*16)     // 30016 bytes (8ch x 2B per cc)
#define SLAB_B  (6*PLANE_B)              // 180096
#define GMAX    17                       // max taps per group
#define FBUF_B  (GMAX*1536)              // 26112
#define SMEMT   (SLAB_B + 2*FBUF_B)      // 232320

#define NTHREADS 512

// fp16 NHWC input: x_h[b][h][w][c48]
__device__ __half g_xh[(size_t)B_ * HH * WW * CIN];
// filter scratch: g_F[b][chunk3][tap49][plane2][n48][mm8] (fp16)
__device__ __half g_F[(size_t)B_ * NCHUNK * TAPS * 2 * 48 * 8];

// ---------------- helpers ----------------
__device__ __forceinline__ void mma_f16(float* c, uint32_t a0, uint32_t a1,
                                        uint32_t a2, uint32_t a3,
                                        uint32_t b0, uint32_t b1) {
    asm volatile(
        "mma.sync.aligned.m16n8k16.row.col.f32.f16.f16.f32 "
        "{%0,%1,%2,%3},{%4,%5,%6,%7},{%8,%9},{%0,%1,%2,%3};"
        : "+f"(c[0]), "+f"(c[1]), "+f"(c[2]), "+f"(c[3])
        : "r"(a0), "r"(a1), "r"(a2), "r"(a3), "r"(b0), "r"(b1));
}
__device__ __forceinline__ void ldsm_x4(uint32_t& r0, uint32_t& r1,
                                        uint32_t& r2, uint32_t& r3, uint32_t addr) {
    asm volatile("ldmatrix.sync.aligned.m8n8.x4.shared.b16 {%0,%1,%2,%3}, [%4];"
                 : "=r"(r0), "=r"(r1), "=r"(r2), "=r"(r3) : "r"(addr));
}
__device__ __forceinline__ void cp16(uint32_t dst, const void* src) {
    asm volatile("cp.async.cg.shared.global [%0], [%1], 16;" :: "r"(dst), "l"(src));
}
#define CP_COMMIT() asm volatile("cp.async.commit_group;" ::: "memory")
#define CP_WAIT0()  asm volatile("cp.async.wait_group 0;" ::: "memory")

// ---------------------------------------------------------------------------
// Kernel T: x (NCHW fp32) -> g_xh (NHWC fp16). Block per (h, b).
// ---------------------------------------------------------------------------
__global__ __launch_bounds__(256)
void nhwc_kernel(const float* __restrict__ x)
{
    __shared__ __half sm[CIN][WW + 2];

    const int h = blockIdx.x;
    const int b = blockIdx.y;
    const int t = threadIdx.x;

    for (int idx = t; idx < CIN * WW; idx += 256) {
        const int c = idx >> 7;
        const int w = idx & 127;
        sm[c][w] = __float2half_rn(x[(((size_t)b * CIN + c) * HH + h) * WW + w]);
    }
    __syncthreads();

    uint4* dst = (uint4*)(g_xh + ((size_t)b * HH + h) * WW * CIN);
    for (int q = t; q < WW * 6; q += 256) {      // piece q = (w, cg): 8 channels
        const int w  = q / 6;
        const int cg = q - w * 6;
        __half tmp[8];
        #pragma unroll
        for (int k = 0; k < 8; ++k) tmp[k] = sm[cg * 8 + k][w];
        dst[q] = *(uint4*)tmp;
    }
}

// ---------------------------------------------------------------------------
// Kernel A: filter generation (register-tiled W reuse, fp16 output).
// ---------------------------------------------------------------------------
__global__ __launch_bounds__(96)
void gen_filters_kernel(const float* __restrict__ theta,
                        const float* __restrict__ W)
{
    __shared__ float bs[TAPS][KDIM];

    const int nh = blockIdx.x;          // 0..1 (24 n each)
    const int ch = blockIdx.y;          // 0..5 (8-channel groups)
    const int b  = blockIdx.z;
    const int t  = threadIdx.x;

    const float th = theta[b];
    const float ct = cosf(th), st = sinf(th);

    for (int e = t; e < TAPS * KDIM; e += 96) {
        const int tap = e / KDIM;
        const int q   = e - tap * KDIM;
        const int i   = tap / SP;
        const int j   = tap % SP;
        const float xj = (float)(j - 3) * (1.0f / 3.0f);
        const float xi = (float)(i - 3) * (1.0f / 3.0f);
        const float Xr = ct * xj - st * xi;
        const float Yr = st * xj + ct * xi;
        const float r2 = Xr * Xr + Yr * Yr;
        const float mask = expf(-fmaxf(r2 - 1.0f, 0.0f) * 5.0f);

        const bool cosp = (q < TAPS);
        const int  qq   = cosp ? q : q - TAPS;
        const int  k    = qq / SP;
        const int  l    = qq % SP;
        const float kk = (k > 3) ? (float)(k - SP) : (float)k;
        const float ll = (l > 3) ? (float)(l - SP) : (float)l;
        const float v  = 2.6927937030769655f;   // pi/7 * 6
        const float ang = kk * v * Xr + ll * v * Yr;
        bs[tap][q] = (cosp ? cosf(ang) : sinf(ang)) * mask;
    }
    __syncthreads();

    const int nn = t >> 3;              // 0..11
    const int mm = t & 7;
    const int m  = ch * 8 + mm;
    const int n0 = nh * 24 + nn;        // and n0+12

    float acc0[TAPS], acc1[TAPS];
    #pragma unroll
    for (int tap = 0; tap < TAPS; ++tap) { acc0[tap] = 0.f; acc1[tap] = 0.f; }

    const float* w0 = W + (size_t)n0 * KDIM * CIN + m;
    const float* w1 = w0 + (size_t)12 * KDIM * CIN;

    #pragma unroll 2
    for (int k = 0; k < KDIM; ++k) {
        const float v0 = w0[(size_t)k * CIN];
        const float v1 = w1[(size_t)k * CIN];
        #pragma unroll
        for (int tap = 0; tap < TAPS; ++tap) {
            const float f = bs[tap][k];
            acc0[tap] = fmaf(f, v0, acc0[tap]);
            acc1[tap] = fmaf(f, v1, acc1[tap]);
        }
    }

    const int chunk = ch >> 1, plane = ch & 1;
    __half* Fo = g_F + ((((size_t)(b * NCHUNK + chunk) * TAPS) * 2 + plane) * 48) * 8 + mm;
    #pragma unroll
    for (int tap = 0; tap < TAPS; ++tap) {
        __half* Ft = Fo + (size_t)tap * (2 * 48 * 8);
        Ft[(size_t)n0 * 8]        = __float2half_rn(acc0[tap]);
        Ft[(size_t)(n0 + 12) * 8] = __float2half_rn(acc1[tap]);
    }
}

// ---------------------------------------------------------------------------
// Kernel B: fp16 m16n8k16 implicit-GEMM grouped conv.
// CTA = (b, 8 rows), 512 thr / 16 warps. Slab: all 48 ch (6 planes), filled
// once via cp.async from NHWC fp16. Filters: double-buffered cp.async staging
// in 9 tap-groups. B frags via 3x ldmatrix.x4.
// ---------------------------------------------------------------------------
__global__ __launch_bounds__(NTHREADS, 1)
void conv_mma_kernel(const float* __restrict__ cbias,
                     float* __restrict__ y)
{
    extern __shared__ __align__(16) unsigned char smraw[];
    const uint32_t smem_u = (uint32_t)__cvta_generic_to_shared(smraw);
    const uint32_t slab_u = smem_u;
    const uint32_t filt_u = smem_u + SLAB_B;

    const int tid  = threadIdx.x;
    const int wid  = tid >> 5;
    const int lane = tid & 31;
    const int b    = blockIdx.x >> 4;
    const int rg   = blockIdx.x & 15;
    const int h0   = rg * RG;

    const int g8 = lane >> 2;          // 0..7 (epilogue px group)
    const int t4 = lane & 3;
    const int rw   = wid >> 1;         // warp row 0..7
    const int col0 = (wid & 1) * 64;   // warp col base

    // ldmatrix lane invariants
    const int a_l16 = lane & 15;
    const int a_pl  = lane >> 4;
    const uint32_t b4off = (uint32_t)(((lane >> 3) & 1) * (48 * 16)
                                      + ((lane >> 4) * 8 + (lane & 7)) * 16);

    float acc[4][6][4];
    #pragma unroll
    for (int mt = 0; mt < 4; ++mt)
        #pragma unroll
        for (int nt = 0; nt < 6; ++nt)
            #pragma unroll
            for (int q = 0; q < 4; ++q)
                acc[mt][nt][q] = 0.0f;

    // ---- prologue: zero slab, then cp.async slab fill + filt group 0 ----
    for (int q = tid; q < SLAB_B / 16; q += NTHREADS)
        ((uint4*)smraw)[q] = make_uint4(0, 0, 0, 0);
    __syncthreads();

    const __half* xhb = g_xh + (size_t)b * HH * WW * CIN;
    #pragma unroll 1
    for (int rr = 0; rr < SLAB_RR; ++rr) {
        const int gr = h0 - 3 + rr;
        if (gr < 0 || gr >= HH) continue;
        const char* src = (const char*)(xhb + (size_t)gr * WW * CIN);
        for (int q = tid; q < WW * 6; q += NTHREADS) {   // q = w*6 + pl
            const int w  = q / 6;
            const int pl = q - w * 6;
            cp16(slab_u + (uint32_t)(((pl * SLAB_RR + rr) * SLAB_CC + 3 + w) * 16),
                 src + q * 16);
        }
    }
    {
        const char* src = (const char*)(g_F + (size_t)(b * NCHUNK) * TAPS * 768);
        for (int q = tid; q < 17 * 96; q += NTHREADS)
            cp16(filt_u + q * 16, src + q * 16);
    }
    CP_COMMIT();
    CP_WAIT0();
    __syncthreads();

    // ---- mainloop: 9 groups (3 chunks x taps {0..16,17..33,34..48}) ----
    #pragma unroll 1
    for (int g = 0; g < 9; ++g) {
        const int chunk = g / 3;
        const int tg    = g - chunk * 3;
        const int ts    = tg * GMAX;                       // 0,17,34
        const int te    = (tg == 2) ? TAPS : ts + GMAX;

        if (g < 8) {   // stage next group into the other buffer (overlapped)
            const int gn  = g + 1;
            const int nck = gn / 3;
            const int nts = (gn - nck * 3) * GMAX;
            const int nte = (gn - nck * 3 == 2) ? TAPS : nts + GMAX;
            const char* src = (const char*)(g_F + ((size_t)(b * NCHUNK + nck) * TAPS + nts) * 768);
            const uint32_t dstb = filt_u + (uint32_t)((gn & 1) * FBUF_B);
            const int pieces = (nte - nts) * 96;
            for (int q = tid; q < pieces; q += NTHREADS)
                cp16(dstb + q * 16, src + q * 16);
            CP_COMMIT();
        }

        const uint32_t fb  = filt_u + (uint32_t)((g & 1) * FBUF_B) + b4off;
        const uint32_t apl = slab_u + (uint32_t)((2 * chunk + a_pl) * PLANE_B + a_l16 * 16);

        int i = ts / SP, j = ts - (ts / SP) * SP;
        #pragma unroll 1
        for (int t = ts; t < te; ++t) {
            const uint32_t bt = fb + (uint32_t)((t - ts) * 1536);
            uint32_t Bf[6][2];
            ldsm_x4(Bf[0][0], Bf[0][1], Bf[1][0], Bf[1][1], bt);
            ldsm_x4(Bf[2][0], Bf[2][1], Bf[3][0], Bf[3][1], bt + 256);
            ldsm_x4(Bf[4][0], Bf[4][1], Bf[5][0], Bf[5][1], bt + 512);
            const uint32_t ar = apl + (uint32_t)((rw + i) * (SLAB_CC * 16) + (col0 + j) * 16);
            #pragma unroll
            for (int mt = 0; mt < 4; ++mt) {
                uint32_t a0, a1, a2, a3;
                ldsm_x4(a0, a1, a2, a3, ar + mt * 256);
                #pragma unroll
                for (int nt = 0; nt < 6; ++nt)
                    mma_f16(acc[mt][nt], a0, a1, a2, a3, Bf[nt][0], Bf[nt][1]);
            }
            if (++j == SP) { j = 0; ++i; }
        }

        if (g < 8) CP_WAIT0();
        __syncthreads();
    }

    // ---- epilogue ----
    const int row = h0 + rw;
    #pragma unroll
    for (int nt = 0; nt < 6; ++nt) {
        const int n  = nt * 8 + 2 * t4;
        const float b0 = __ldg(&cbias[n]);
        const float b1 = __ldg(&cbias[n + 1]);
        float* y0 = y + (((size_t)b * COUT + n) * HH + row) * WW;
        float* y1 = y0 + (size_t)HH * WW;
        #pragma unroll
        for (int mt = 0; mt < 4; ++mt) {
            const int px = col0 + mt * 16 + g8;
            y0[px]     = acc[mt][nt][0] + b0;
            y1[px]     = acc[mt][nt][1] + b1;
            y0[px + 8] = acc[mt][nt][2] + b0;
            y1[px + 8] = acc[mt][nt][3] + b1;
        }
    }
}

// ---------------------------------------------------------------------------
extern "C" void kernel_launch(void* const* d_in, const int* in_sizes, int n_in,
                              void* d_out, int out_size)
{
    const float* x     = (const float*)d_in[0];  // (16,48,128,128)
    const float* theta = (const float*)d_in[1];  // (16,1)
    const float* wts   = (const float*)d_in[2];  // (48,98,48)
    const float* cbias = (const float*)d_in[3];  // (1,48,1,1)
    float*       y     = (float*)d_out;          // (16,48,128,128)

    (void)in_sizes; (void)n_in; (void)out_size;

    static int smem_set = 0;
    if (!smem_set) {
        cudaFuncSetAttribute(conv_mma_kernel,
                             cudaFuncAttributeMaxDynamicSharedMemorySize, SMEMT);
        smem_set = 1;
    }

    dim3 tgrid(HH, B_);
    nhwc_kernel<<<tgrid, 256>>>(x);
    dim3 ggrid(2, 6, B_);
    gen_filters_kernel<<<ggrid, 96>>>(theta, wts);
    conv_mma_kernel<<<B_ * 16, NTHREADS, SMEMT>>>(cbias, y);
}